// round 3
// baseline (speedup 1.0000x reference)
#include <cuda_runtime.h>
#include <cstdint>

// Problem constants (fixed by the reference):
//   COMPLEXES=2048, RESY=RESX=16, FEAT=64, P=RATE*RATE=256
// map: [C, 16, 16, 64] f32 ; u,v: [C, 256] f32 ; out: [C, 256, 64] f32

constexpr int C_    = 2048;
constexpr int H_    = 16;
constexpr int W_    = 16;
constexpr int F_    = 64;
constexpr int P_    = 256;
constexpr int TILE_FLOATS = H_ * W_ * F_;            // 16384 floats = 64 KB
constexpr int TILE_CHUNKS = TILE_FLOATS / 4;         // 4096 x 16B
constexpr int THREADS     = 1024;
constexpr int GRID        = 148;                     // persistent: 1 CTA/SM

// Dynamic smem:
//   tiles[2][16384] floats  (2 x 64 KB, double buffer)
//   s_off[256] int, s_fx[256], s_fy[256]
constexpr int SMEM_TOTAL = 2 * TILE_FLOATS * 4 + 3 * P_ * 4;   // 134144 B

__device__ __forceinline__ void cp_async16(uint32_t smem_addr, const void* gptr) {
    asm volatile("cp.async.cg.shared.global [%0], [%1], 16;\n"
                 :: "r"(smem_addr), "l"(gptr) : "memory");
}
__device__ __forceinline__ void cp_async_commit() {
    asm volatile("cp.async.commit_group;\n" ::: "memory");
}
__device__ __forceinline__ void cp_async_wait1() {
    asm volatile("cp.async.wait_group 1;\n" ::: "memory");
}

__global__ __launch_bounds__(THREADS, 1)
void ngf_texture_fetch_kernel(const float* __restrict__ gmap,
                              const float* __restrict__ gu,
                              const float* __restrict__ gv,
                              float* __restrict__ gout)
{
    extern __shared__ __align__(16) float smem[];
    float* tile0 = smem;                               // 16384 floats
    float* tile1 = smem + TILE_FLOATS;                 // 16384 floats
    int*   s_off = (int*)(smem + 2 * TILE_FLOATS);     // 256
    float* s_fx  = (float*)(s_off + P_);               // 256
    float* s_fy  = s_fx + P_;                          // 256

    const int t   = threadIdx.x;
    const int bid = blockIdx.x;

    // Precompute shared-space addresses for this thread's 4 cp.async chunks.
    uint32_t smem_base0 = (uint32_t)__cvta_generic_to_shared(tile0) + t * 16u;
    uint32_t smem_base1 = (uint32_t)__cvta_generic_to_shared(tile1) + t * 16u;

    // ---- prologue: prefetch first complex's tile into buf0 ----
    {
        const int c0 = bid;   // bid < 148 <= 2048, always valid
        const float4* src = (const float4*)(gmap + (size_t)c0 * TILE_FLOATS);
        #pragma unroll
        for (int k = 0; k < TILE_CHUNKS / THREADS; ++k)      // 4 chunks/thread
            cp_async16(smem_base0 + k * (THREADS * 16u), src + t + k * THREADS);
        cp_async_commit();
    }

    const int fq = (t & 15);          // feature quad 0..15
    const int sl = (t >> 4);          // sample lane 0..63

    // ---- persistent loop over complexes (stride GRID) ----
    int it_idx = 0;
    for (int c = bid; c < C_; c += GRID, ++it_idx) {
        const int      cur   = it_idx & 1;
        const float*   tileC = cur ? tile1 : tile0;
        const uint32_t nextB = cur ? smem_base0 : smem_base1;

        // 1) issue prefetch of next complex into the other buffer
        const int cn = c + GRID;
        if (cn < C_) {
            const float4* src = (const float4*)(gmap + (size_t)cn * TILE_FLOATS);
            #pragma unroll
            for (int k = 0; k < TILE_CHUNKS / THREADS; ++k)
                cp_async16(nextB + k * (THREADS * 16u), src + t + k * THREADS);
        }
        cp_async_commit();     // always commit (possibly empty group)

        // 2) wait until the current buffer's group has landed
        cp_async_wait1();

        // 3) per-sample params (first 256 threads; one sample each)
        if (t < P_) {
            const float uu = gu[(size_t)c * P_ + t];
            const float vv = gv[(size_t)c * P_ + t];
            const float x = uu * (float)(W_ - 1);
            const float y = vv * (float)(H_ - 1);
            int x0 = (int)floorf(x);
            int y0 = (int)floorf(y);
            x0 = min(max(x0, 0), W_ - 2);
            y0 = min(max(y0, 0), H_ - 2);
            s_fx[t]  = x - (float)x0;
            s_fy[t]  = y - (float)y0;
            s_off[t] = (y0 * W_ + x0) * F_;
        }
        __syncthreads();       // tile + params visible to all

        // 4) bilinear gather + coalesced float4 stores
        float4* out4 = (float4*)(gout + (size_t)c * P_ * F_);
        #pragma unroll
        for (int i = 0; i < P_ / 64; ++i) {                 // 4 iterations
            const int s   = i * 64 + sl;
            const int off = s_off[s] + fq * 4;
            const float fx = s_fx[s];
            const float fy = s_fy[s];

            const float4 g00 = *(const float4*)(tileC + off);
            const float4 g01 = *(const float4*)(tileC + off + F_);
            const float4 g10 = *(const float4*)(tileC + off + W_ * F_);
            const float4 g11 = *(const float4*)(tileC + off + W_ * F_ + F_);

            const float w11 = fx * fy;
            const float w01 = fx - w11;               // fx*(1-fy)
            const float w10 = fy - w11;               // (1-fx)*fy
            const float w00 = 1.0f - fx - fy + w11;

            float4 r;
            r.x = g00.x * w00 + g01.x * w01 + g10.x * w10 + g11.x * w11;
            r.y = g00.y * w00 + g01.y * w01 + g10.y * w10 + g11.y * w11;
            r.z = g00.z * w00 + g01.z * w01 + g10.z * w10 + g11.z * w11;
            r.w = g00.w * w00 + g01.w * w01 + g10.w * w10 + g11.w * w11;

            out4[s * (F_ / 4) + fq] = r;
        }
        __syncthreads();       // done reading tileC & params before overwrite
    }
}

extern "C" void kernel_launch(void* const* d_in, const int* in_sizes, int n_in,
                              void* d_out, int out_size)
{
    const float* gmap = (const float*)d_in[0];
    const float* gu   = (const float*)d_in[1];
    const float* gv   = (const float*)d_in[2];
    float* gout       = (float*)d_out;

    cudaFuncSetAttribute(ngf_texture_fetch_kernel,
                         cudaFuncAttributeMaxDynamicSharedMemorySize, SMEM_TOTAL);

    ngf_texture_fetch_kernel<<<GRID, THREADS, SMEM_TOTAL>>>(gmap, gu, gv, gout);
}

// round 4
// speedup vs baseline: 1.1247x; 1.1247x over previous
#include <cuda_runtime.h>
#include <cstdint>

// COMPLEXES=2048, RESY=RESX=16, FEAT=64, P=256
// map: [C,16,16,64] f32 ; u,v: [C,256] f32 ; out: [C,256,64] f32

constexpr int C_    = 2048;
constexpr int H_    = 16;
constexpr int W_    = 16;
constexpr int F_    = 64;
constexpr int P_    = 256;
constexpr int TILE_FLOATS = H_ * W_ * F_;            // 16384 floats = 64 KB
constexpr int TILE_BYTES  = TILE_FLOATS * 4;         // 65536
constexpr int THREADS     = 256;
constexpr int CTAS_PER_SM = 3;
constexpr int GRID        = 148 * CTAS_PER_SM;       // 444 persistent CTAs

// Dyn smem: tile (64 KB) + s_off/s_fx/s_fy (3 KB) = 67.6 KB -> 3 CTAs/SM
constexpr int SMEM_TOTAL = TILE_BYTES + 3 * P_ * 4;

__device__ __forceinline__ void cp_async16(uint32_t smem_addr, const void* gptr) {
    asm volatile("cp.async.cg.shared.global [%0], [%1], 16;\n"
                 :: "r"(smem_addr), "l"(gptr) : "memory");
}
__device__ __forceinline__ void cp_async_commit() {
    asm volatile("cp.async.commit_group;\n" ::: "memory");
}
__device__ __forceinline__ void cp_async_wait0() {
    asm volatile("cp.async.wait_group 0;\n" ::: "memory");
}
__device__ __forceinline__ void l2_prefetch_bulk(const void* gptr, uint32_t bytes) {
    asm volatile("cp.async.bulk.prefetch.L2.global [%0], %1;\n"
                 :: "l"(gptr), "r"(bytes) : "memory");
}

__global__ __launch_bounds__(THREADS)
void ngf_texture_fetch_kernel(const float* __restrict__ gmap,
                              const float* __restrict__ gu,
                              const float* __restrict__ gv,
                              float* __restrict__ gout)
{
    extern __shared__ __align__(16) float smem[];
    float* tile  = smem;                              // 16384 floats
    int*   s_off = (int*)(smem + TILE_FLOATS);        // 256
    float* s_fx  = (float*)(s_off + P_);              // 256
    float* s_fy  = s_fx + P_;                         // 256

    const int t   = threadIdx.x;
    const int bid = blockIdx.x;

    // Per-thread smem base for staging: 16 chunks of 16B, stride 256 chunks.
    const uint32_t smem_st = (uint32_t)__cvta_generic_to_shared(tile) + t * 16u;

    const int fq = (t & 15);          // feature quad 0..15
    const int sl = (t >> 4);          // sample lane 0..15

    for (int c = bid; c < C_; c += GRID) {
        // 1) stage this complex's 64KB tile via cp.async (no reg round-trip)
        {
            const float4* src = (const float4*)(gmap + (size_t)c * TILE_FLOATS);
            #pragma unroll
            for (int k = 0; k < (TILE_FLOATS / 4) / THREADS; ++k)   // 16
                cp_async16(smem_st + k * (THREADS * 16u), src + t + k * THREADS);
            cp_async_commit();
        }

        // 2) hint-prefetch the NEXT complex's tile into L2 (async, no tracking)
        const int cn = c + GRID;
        if (t == 0 && cn < C_) {
            l2_prefetch_bulk(gmap + (size_t)cn * TILE_FLOATS, TILE_BYTES);
        }

        // 3) per-sample params while the tile streams in
        {
            const float uu = gu[(size_t)c * P_ + t];
            const float vv = gv[(size_t)c * P_ + t];
            const float x = uu * (float)(W_ - 1);
            const float y = vv * (float)(H_ - 1);
            int x0 = (int)floorf(x);
            int y0 = (int)floorf(y);
            x0 = min(max(x0, 0), W_ - 2);
            y0 = min(max(y0, 0), H_ - 2);
            s_fx[t]  = x - (float)x0;
            s_fy[t]  = y - (float)y0;
            s_off[t] = (y0 * W_ + x0) * F_;
        }

        // 4) wait for tile, publish params
        cp_async_wait0();
        __syncthreads();

        // 5) bilinear gather from smem + fully coalesced float4 stores
        float4* out4 = (float4*)(gout + (size_t)c * P_ * F_);
        #pragma unroll
        for (int i = 0; i < P_ / 16; ++i) {             // 16 iterations
            const int s   = i * 16 + sl;
            const int off = s_off[s] + fq * 4;
            const float fx = s_fx[s];
            const float fy = s_fy[s];

            const float4 g00 = *(const float4*)(tile + off);
            const float4 g01 = *(const float4*)(tile + off + F_);
            const float4 g10 = *(const float4*)(tile + off + W_ * F_);
            const float4 g11 = *(const float4*)(tile + off + W_ * F_ + F_);

            const float w11 = fx * fy;
            const float w01 = fx - w11;               // fx*(1-fy)
            const float w10 = fy - w11;               // (1-fx)*fy
            const float w00 = 1.0f - fx - fy + w11;

            float4 r;
            r.x = g00.x * w00 + g01.x * w01 + g10.x * w10 + g11.x * w11;
            r.y = g00.y * w00 + g01.y * w01 + g10.y * w10 + g11.y * w11;
            r.z = g00.z * w00 + g01.z * w01 + g10.z * w10 + g11.z * w11;
            r.w = g00.w * w00 + g01.w * w01 + g10.w * w10 + g11.w * w11;

            out4[s * (F_ / 4) + fq] = r;
        }

        // 6) protect tile + params before next iteration overwrites them
        __syncthreads();
    }
}

extern "C" void kernel_launch(void* const* d_in, const int* in_sizes, int n_in,
                              void* d_out, int out_size)
{
    const float* gmap = (const float*)d_in[0];
    const float* gu   = (const float*)d_in[1];
    const float* gv   = (const float*)d_in[2];
    float* gout       = (float*)d_out;

    cudaFuncSetAttribute(ngf_texture_fetch_kernel,
                         cudaFuncAttributeMaxDynamicSharedMemorySize, SMEM_TOTAL);

    ngf_texture_fetch_kernel<<<GRID, THREADS, SMEM_TOTAL>>>(gmap, gu, gv, gout);
}

// round 6
// speedup vs baseline: 1.3022x; 1.1579x over previous
#include <cuda_runtime.h>
#include <cstdint>

// COMPLEXES=2048, RESY=RESX=16, FEAT=64, P=256
// map: [C,16,16,64] f32 ; u,v: [C,256] f32 ; out: [C,256,64] f32
//
// Work item = (complex, feature-half). 4096 items. Tile per item = 16x16x32 f32
// = 32 KB, double-buffered in smem -> staging of item i+1 overlaps compute of i.

constexpr int C_    = 2048;
constexpr int H_    = 16;
constexpr int W_    = 16;
constexpr int F_    = 64;
constexpr int FH_   = 32;                      // features per half
constexpr int P_    = 256;
constexpr int ITEMS = C_ * 2;                  // 4096
constexpr int HALF_FLOATS = H_ * W_ * FH_;     // 8192 floats = 32 KB
constexpr int HALF_CHUNKS = HALF_FLOATS / 4;   // 2048 x 16B
constexpr int THREADS     = 256;
constexpr int GRID        = 148 * 3;           // 444 persistent CTAs

// Dyn smem: 2 x 32KB tiles + 2 x (off/fx/fy)[256] = 71680 B -> 3 CTAs/SM
constexpr int SMEM_TOTAL = 2 * HALF_FLOATS * 4 + 2 * 3 * P_ * 4;

__device__ __forceinline__ void cp_async16(uint32_t smem_addr, const void* gptr) {
    asm volatile("cp.async.cg.shared.global [%0], [%1], 16;\n"
                 :: "r"(smem_addr), "l"(gptr) : "memory");
}
__device__ __forceinline__ void cp_async_commit() {
    asm volatile("cp.async.commit_group;\n" ::: "memory");
}
__device__ __forceinline__ void cp_async_wait1() {
    asm volatile("cp.async.wait_group 1;\n" ::: "memory");
}

__global__ __launch_bounds__(THREADS)
void ngf_texture_fetch_kernel(const float* __restrict__ gmap,
                              const float* __restrict__ gu,
                              const float* __restrict__ gv,
                              float* __restrict__ gout)
{
    extern __shared__ __align__(16) float smem[];
    float* tiles = smem;                                 // [2][8192]
    int*   s_off = (int*)(smem + 2 * HALF_FLOATS);       // [2][256]
    float* s_fx  = (float*)(s_off + 2 * P_);             // [2][256]
    float* s_fy  = s_fx + 2 * P_;                        // [2][256]

    const int t   = threadIdx.x;
    const int bid = blockIdx.x;

    const uint32_t tile_sm0 =
        (uint32_t)__cvta_generic_to_shared(tiles) + t * 16u;
    const uint32_t tile_stride = (uint32_t)(HALF_FLOATS * 4);   // 32 KB

    const int fq = (t & 7);           // feature quad 0..7 (4 floats each)
    const int sl = (t >> 3);          // sample lane 0..31

    // ---- stage helper: item w -> buffer b ----
    auto stage = [&](int w, int b) {
        const int c = w >> 1;
        const int h = w & 1;
        // chunk j (0..2047): cell = j>>3, wi = j&7
        // float4 index into this complex's map: cell*16 + h*8 + wi
        const float4* base4 = (const float4*)(gmap + (size_t)c * (H_ * W_ * F_));
        const uint32_t dst0 = tile_sm0 + (uint32_t)b * tile_stride;
        #pragma unroll
        for (int k = 0; k < HALF_CHUNKS / THREADS; ++k) {        // 8
            const int j    = k * THREADS + t;
            const int cell = j >> 3;
            const int wi   = j & 7;
            cp_async16(dst0 + k * (THREADS * 16u), base4 + cell * 16 + h * 8 + wi);
        }
    };

    auto params = [&](int w, int b) {
        const int c = w >> 1;
        const float uu = gu[(size_t)c * P_ + t];
        const float vv = gv[(size_t)c * P_ + t];
        const float x = uu * (float)(W_ - 1);
        const float y = vv * (float)(H_ - 1);
        int x0 = (int)floorf(x);
        int y0 = (int)floorf(y);
        x0 = min(max(x0, 0), W_ - 2);
        y0 = min(max(y0, 0), H_ - 2);
        s_fx[b * P_ + t]  = x - (float)x0;
        s_fy[b * P_ + t]  = y - (float)y0;
        s_off[b * P_ + t] = (y0 * W_ + x0) * FH_;
    };

    // ---- prologue: stage + params for first item into buffer 0 ----
    {
        const int w0 = bid;               // bid < 444 < 4096
        stage(w0, 0);
        cp_async_commit();
        params(w0, 0);
    }

    // ---- persistent loop ----
    int b = 0;
    for (int w = bid; w < ITEMS; w += GRID, b ^= 1) {
        // 1) stage next item into the other buffer (overlaps this compute)
        const int wn = w + GRID;
        if (wn < ITEMS) {
            stage(wn, b ^ 1);
            params(wn, b ^ 1);
        }
        cp_async_commit();                // one group per iteration, always

        // 2) current tile landed (non-blocking in steady state)
        cp_async_wait1();
        __syncthreads();                  // cross-thread visibility of tile+params

        // 3) bilinear gather + coalesced float4 stores
        const int c = w >> 1;
        const int h = w & 1;
        const float* tile = tiles + b * HALF_FLOATS;
        const int*   off_ = s_off + b * P_;
        const float* fx_  = s_fx + b * P_;
        const float* fy_  = s_fy + b * P_;
        float4* out4 = (float4*)(gout + (size_t)c * P_ * F_) + h * (FH_ / 4);

        #pragma unroll
        for (int i = 0; i < P_ / 32; ++i) {            // 8 iterations
            const int s   = i * 32 + sl;
            const int off = off_[s] + fq * 4;
            const float fx = fx_[s];
            const float fy = fy_[s];

            const float4 g00 = *(const float4*)(tile + off);
            const float4 g01 = *(const float4*)(tile + off + FH_);
            const float4 g10 = *(const float4*)(tile + off + W_ * FH_);
            const float4 g11 = *(const float4*)(tile + off + W_ * FH_ + FH_);

            const float w11 = fx * fy;
            const float w01 = fx - w11;               // fx*(1-fy)
            const float w10 = fy - w11;               // (1-fx)*fy
            const float w00 = 1.0f - fx - fy + w11;

            float4 r;
            r.x = g00.x * w00 + g01.x * w01 + g10.x * w10 + g11.x * w11;
            r.y = g00.y * w00 + g01.y * w01 + g10.y * w10 + g11.y * w11;
            r.z = g00.z * w00 + g01.z * w01 + g10.z * w10 + g11.z * w11;
            r.w = g00.w * w00 + g01.w * w01 + g10.w * w10 + g11.w * w11;

            out4[s * (F_ / 4) + fq] = r;
        }

        // 4) all reads of tile[b]/params[b] done before next iter overwrites
        __syncthreads();
    }
}

extern "C" void kernel_launch(void* const* d_in, const int* in_sizes, int n_in,
                              void* d_out, int out_size)
{
    const float* gmap = (const float*)d_in[0];
    const float* gu   = (const float*)d_in[1];
    const float* gv   = (const float*)d_in[2];
    float* gout       = (float*)d_out;

    cudaFuncSetAttribute(ngf_texture_fetch_kernel,
                         cudaFuncAttributeMaxDynamicSharedMemorySize, SMEM_TOTAL);

    ngf_texture_fetch_kernel<<<GRID, THREADS, SMEM_TOTAL>>>(gmap, gu, gv, gout);
}